// round 13
// baseline (speedup 1.0000x reference)
#include <cuda_runtime.h>
#include <math.h>

// Problem constants (fixed by reference setup_inputs)
#define SN      10
#define ITERS   100
#define WARMUP  4
#define HWPIX   (128*128)
#define LOG2E   1.4426950408889634f
#define LN2     0.6931471805599453f

// Global accumulators: [k*16] for k in 0..4 -> each on its own 128B line so the
// five atomic streams hit different LTS slices instead of serializing on one.
// [0]=n_neg [1]=n_pos [2]=sumsq_neg [3]=sumsq_posneg [4]=loss_pos
__device__ double g_acc[5 * 16] = {0};
__device__ unsigned int g_ticket = 0;

// ---- packed f32x2 helpers (Blackwell sm_100+) ----
__device__ __forceinline__ unsigned long long f2_mul(unsigned long long a, unsigned long long b) {
    unsigned long long d;
    asm("mul.rn.f32x2 %0, %1, %2;" : "=l"(d) : "l"(a), "l"(b));
    return d;
}
__device__ __forceinline__ unsigned long long f2_fma(unsigned long long a, unsigned long long b, unsigned long long c) {
    unsigned long long d;
    asm("fma.rn.f32x2 %0, %1, %2, %3;" : "=l"(d) : "l"(a), "l"(b), "l"(c));
    return d;
}
__device__ __forceinline__ unsigned long long f2_add(unsigned long long a, unsigned long long b) {
    unsigned long long d;
    asm("add.rn.f32x2 %0, %1, %2;" : "=l"(d) : "l"(a), "l"(b));
    return d;
}
__device__ __forceinline__ unsigned long long f2_pack(float lo, float hi) {
    unsigned long long d;
    asm("mov.b64 %0, {%1, %2};" : "=l"(d) : "f"(lo), "f"(hi));
    return d;
}
__device__ __forceinline__ void f2_unpack(unsigned long long v, float& lo, float& hi) {
    asm("mov.b64 {%0, %1}, %2;" : "=f"(lo), "=f"(hi) : "l"(v));
}
__device__ __forceinline__ float frcp(float x) {
    float y; asm("rcp.approx.f32 %0, %1;" : "=f"(y) : "f"(x)); return y;
}
__device__ __forceinline__ float fex2(float x) {
    float y; asm("ex2.approx.f32 %0, %1;" : "=f"(y) : "f"(x)); return y;
}

// 5 CTAs/SM (102-reg cap, 20 warps/SM). Register diet: offsets live in smem
// for setup/epilogue (never loop-carried), col pass uses a single accumulator
// set. Hot live set ~95 regs: K2(50)+beta(10)+alpha(10)+e(10)+stats/ptrs(~15).
__global__ __launch_bounds__(128, 5) void ol_main_kernel(
    const float* __restrict__ outp_g,
    const float* __restrict__ tgt_g,
    const float* __restrict__ msk_g,
    float* __restrict__ result,
    int npix)
{
    __shared__ float s_oy[SN][128];   // offsets pre-scaled by log2(e), [m][tid]
    __shared__ float s_ox[SN][128];
    __shared__ float s_part[5][4];    // per-warp partials for the block reduction

    const int tid = threadIdx.x;
    int p = blockIdx.x * blockDim.x + tid;

    float negf = 0.f, posf = 0.f, sumsq = 0.f, pnsq = 0.f, lp = 0.f;

    if (p < npix) {
        const int b  = p >> 14;            // HWPIX = 16384
        const int hw = p & (HWPIX - 1);
        const int h  = hw >> 7;
        const int w  = hw & 127;

        const float* outp = outp_g + (size_t)b * 36 * HWPIX + hw;
        const float* tgtp = tgt_g  + (size_t)b * 20 * HWPIX + hw;
        const float* mskp = msk_g  + (size_t)b * 10 * HWPIX + hw;

        // ---- pos/neg from mask ----
        float msum = 0.f;
        #pragma unroll
        for (int s = 0; s < SN; s++) msum += mskp[s * HWPIX];
        posf = (msum >= 1.0f) ? 1.0f : 0.0f;
        negf = 1.0f - posf;

        // ---- offsets (scaled by log2(e)) written straight to smem; no
        //      register copy survives this loop ----
        #pragma unroll
        for (int m = 0; m < 18; m++) {
            const int head  = (m >= 9) ? 1 : 0;
            const int local = m - head * 9;
            const int i = local / 3;
            const int j = local - i * 3;
            const int cy = head * 18 + local;        // d=0
            const float vy = outp[cy * HWPIX];
            const float vx = outp[(cy + 9) * HWPIX]; // d=1
            sumsq += vy * vy + vx * vx;
            const float oyv = vy + (float)(i - 1) + (float)h;
            const float oxv = vx + (float)(j - 1) + (float)w;
            if (m < SN) {
                s_oy[m][tid] = oyv * LOG2E;
                s_ox[m][tid] = oxv * LOG2E;
            } else {
                pnsq += oyv * oyv + oxv * oxv;
            }
        }

        // ---- Gibbs kernel K[s][m] = 2^(rmin - c2[s][m]) (row max = 1),
        //      offsets read from smem to cap setup-phase register pressure ----
        unsigned long long K2[SN][5];
        #pragma unroll
        for (int s = 0; s < SN; s++) {
            const float tys = tgtp[s * HWPIX] * LOG2E;
            const float txs = tgtp[(SN + s) * HWPIX] * LOG2E;
            float c[SN];
            float rm = 3.4e38f;
            #pragma unroll
            for (int m = 0; m < SN; m++) {
                c[m] = fabsf(tys - s_oy[m][tid]) + fabsf(txs - s_ox[m][tid]);
                rm = fminf(rm, c[m]);
            }
            #pragma unroll
            for (int k = 0; k < 5; k++)
                K2[s][k] = f2_pack(fex2(rm - c[2 * k]), fex2(rm - c[2 * k + 1]));
        }

        // ---- Sinkhorn, rescaled: fixed point alpha.(K beta) = 1, beta.(K^T alpha) = 1.
        //      WARMUP exact-rcp iterations enter the Newton basin, then division-free
        //      Newton-coupled scaling (0 MUFU / iteration). ----
        float alpha[SN];
        unsigned long long beta[5];
        #pragma unroll
        for (int k = 0; k < 5; k++) beta[k] = f2_pack(20.0f, 20.0f);  // v0 = 0

        #pragma unroll
        for (int wu = 0; wu < WARMUP; wu++) {
            #pragma unroll
            for (int s = 0; s < SN; s++) {
                unsigned long long t0 = f2_mul(K2[s][0], beta[0]);
                unsigned long long t1 = f2_mul(K2[s][1], beta[1]);
                t0 = f2_fma(K2[s][2], beta[2], t0);
                t1 = f2_fma(K2[s][3], beta[3], t1);
                t0 = f2_fma(K2[s][4], beta[4], t0);
                float lo, hi; f2_unpack(f2_add(t0, t1), lo, hi);
                alpha[s] = frcp(lo + hi);
            }
            unsigned long long e[5];
            {
                const unsigned long long a0 = f2_pack(alpha[0], alpha[0]);
                #pragma unroll
                for (int k = 0; k < 5; k++) e[k] = f2_mul(K2[0][k], a0);
            }
            #pragma unroll
            for (int s = 1; s < SN; s++) {
                const unsigned long long aa = f2_pack(alpha[s], alpha[s]);
                #pragma unroll
                for (int k = 0; k < 5; k++) e[k] = f2_fma(K2[s][k], aa, e[k]);
            }
            #pragma unroll
            for (int k = 0; k < 5; k++) {
                float lo, hi; f2_unpack(e[k], lo, hi);
                beta[k] = f2_pack(frcp(lo), frcp(hi));
            }
        }

        // Newton-mode main loop; residual read off the Newton factor (|f-1| = |1 - d*alpha|).
        int it = 0;
        while (true) {
            bool conv = true;
            #pragma unroll
            for (int s = 0; s < SN; s++) {
                unsigned long long t0 = f2_mul(K2[s][0], beta[0]);
                unsigned long long t1 = f2_mul(K2[s][1], beta[1]);
                t0 = f2_fma(K2[s][2], beta[2], t0);
                t1 = f2_fma(K2[s][3], beta[3], t1);
                t0 = f2_fma(K2[s][4], beta[4], t0);
                float lo, hi; f2_unpack(f2_add(t0, t1), lo, hi);
                const float d = lo + hi;
                const float f = fmaf(-d, alpha[s], 2.0f);   // Newton factor
                conv = conv && (fabsf(f - 1.0f) <= 1e-4f);
                alpha[s] *= f;
            }
            unsigned long long e[5];
            {
                const unsigned long long a0 = f2_pack(alpha[0], alpha[0]);
                #pragma unroll
                for (int k = 0; k < 5; k++) e[k] = f2_mul(K2[0][k], a0);
            }
            #pragma unroll
            for (int s = 1; s < SN; s++) {
                const unsigned long long aa = f2_pack(alpha[s], alpha[s]);
                #pragma unroll
                for (int k = 0; k < 5; k++) e[k] = f2_fma(K2[s][k], aa, e[k]);
            }
            #pragma unroll
            for (int k = 0; k < 5; k++) {
                float lo, hi; f2_unpack(e[k], lo, hi);
                float b0, b1; f2_unpack(beta[k], b0, b1);
                b0 = b0 * fmaf(-lo, b0, 2.0f);   // Newton rcp step for beta
                b1 = b1 * fmaf(-hi, b1, 2.0f);
                beta[k] = f2_pack(b0, b1);
            }
            if (++it >= ITERS) break;
            if (__all_sync(__activemask(), conv)) break;
        }

        // ---- loss_pos = sum_s mask_s * alpha_s * sum_m K[s][m]*beta_m*cost[s][m]
        //      (offsets read back from smem; costs in log2 units, one LN2 rescale) ----
        #pragma unroll
        for (int s = 0; s < SN; s++) {
            const float tys = tgtp[s * HWPIX] * LOG2E;
            const float txs = tgtp[(SN + s) * HWPIX] * LOG2E;
            unsigned long long acc = 0ull;   // packed (0,0)
            #pragma unroll
            for (int k = 0; k < 5; k++) {
                const float c0 = fabsf(tys - s_oy[2 * k][tid])     + fabsf(txs - s_ox[2 * k][tid]);
                const float c1 = fabsf(tys - s_oy[2 * k + 1][tid]) + fabsf(txs - s_ox[2 * k + 1][tid]);
                acc = f2_fma(f2_mul(K2[s][k], beta[k]), f2_pack(c0, c1), acc);
            }
            float lo, hi; f2_unpack(acc, lo, hi);
            const float ms = mskp[s * HWPIX];  // reload (L2 hit)
            lp = fmaf(ms * alpha[s], lo + hi, lp);
        }
        lp *= LN2;
        sumsq *= negf;
        pnsq  *= posf;
    }

    // ---- hierarchical reduction: warp shuffle -> smem -> ONE thread's atomics
    //      onto 128B-padded accumulators (proven 8us win in R10) ----
    float vals[5] = { negf, posf, sumsq, pnsq, lp };
    const int wid = tid >> 5;
    const int lid = tid & 31;
    #pragma unroll
    for (int k = 0; k < 5; k++) {
        float v = vals[k];
        #pragma unroll
        for (int off = 16; off; off >>= 1)
            v += __shfl_xor_sync(0xffffffffu, v, off);
        if (lid == 0) s_part[k][wid] = v;
    }
    __syncthreads();
    if (tid < 5) {
        const float bsum = s_part[tid][0] + s_part[tid][1]
                         + s_part[tid][2] + s_part[tid][3];
        atomicAdd(&g_acc[tid * 16], (double)bsum);
    }

    // ---- fused finalize: last block computes the scalar result and resets state ----
    __syncthreads();
    if (tid == 0) {
        __threadfence();
        const unsigned t = atomicAdd(&g_ticket, 1u);
        if (t == gridDim.x - 1) {
            __threadfence();
            const double n_neg = g_acc[0 * 16];
            const double n_pos = g_acc[1 * 16];
            const double loss_neg     = sqrt(g_acc[2 * 16]) / n_neg;
            const double loss_pos_neg = sqrt(g_acc[3 * 16]) / n_pos;
            result[0] = (float)((loss_neg + loss_pos_neg) * 100.0
                                + g_acc[4 * 16] / (n_pos + 0.0001));
            #pragma unroll
            for (int k = 0; k < 5; k++) g_acc[k * 16] = 0.0;
            __threadfence();
            g_ticket = 0u;
        }
    }
}

extern "C" void kernel_launch(void* const* d_in, const int* in_sizes, int n_in,
                              void* d_out, int out_size) {
    const float* out_t  = (const float*)d_in[0];   // (B, 36, 128, 128)
    const float* target = (const float*)d_in[1];   // (B, 20, 128, 128)
    const float* mask   = (const float*)d_in[2];   // (B, 10, 128, 128)

    const int npix = in_sizes[2] / SN;             // B * H * W
    const int threads = 128;
    const int blocks = (npix + threads - 1) / threads;

    ol_main_kernel<<<blocks, threads>>>(out_t, target, mask, (float*)d_out, npix);
}

// round 15
// speedup vs baseline: 1.5637x; 1.5637x over previous
#include <cuda_runtime.h>
#include <math.h>

// Problem constants (fixed by reference setup_inputs)
#define SN      10
#define ITERS   100
#define WARMUP  4
#define HWPIX   (128*128)
#define LOG2E   1.4426950408889634f
#define LN2     0.6931471805599453f

// Global accumulators: [k*16] for k in 0..4 -> each on its own 128B line so the
// five atomic streams hit different LTS slices instead of serializing on one.
// [0]=n_neg [1]=n_pos [2]=sumsq_neg [3]=sumsq_posneg [4]=loss_pos
__device__ double g_acc[5 * 16] = {0};
__device__ unsigned int g_ticket = 0;

// ---- packed f32x2 helpers (Blackwell sm_100+) ----
__device__ __forceinline__ unsigned long long f2_mul(unsigned long long a, unsigned long long b) {
    unsigned long long d;
    asm("mul.rn.f32x2 %0, %1, %2;" : "=l"(d) : "l"(a), "l"(b));
    return d;
}
__device__ __forceinline__ unsigned long long f2_fma(unsigned long long a, unsigned long long b, unsigned long long c) {
    unsigned long long d;
    asm("fma.rn.f32x2 %0, %1, %2, %3;" : "=l"(d) : "l"(a), "l"(b), "l"(c));
    return d;
}
__device__ __forceinline__ unsigned long long f2_add(unsigned long long a, unsigned long long b) {
    unsigned long long d;
    asm("add.rn.f32x2 %0, %1, %2;" : "=l"(d) : "l"(a), "l"(b));
    return d;
}
__device__ __forceinline__ unsigned long long f2_pack(float lo, float hi) {
    unsigned long long d;
    asm("mov.b64 %0, {%1, %2};" : "=l"(d) : "f"(lo), "f"(hi));
    return d;
}
__device__ __forceinline__ void f2_unpack(unsigned long long v, float& lo, float& hi) {
    asm("mov.b64 {%0, %1}, %2;" : "=f"(lo), "=f"(hi) : "l"(v));
}
__device__ __forceinline__ float frcp(float x) {
    float y; asm("rcp.approx.f32 %0, %1;" : "=f"(y) : "f"(x)); return y;
}
__device__ __forceinline__ float fex2(float x) {
    float y; asm("ex2.approx.f32 %0, %1;" : "=f"(y) : "f"(x)); return y;
}
// Clamped Newton factor: guarantees the reciprocal recurrence stays inside its
// convergence basin regardless of how far the previous iterate drifted.
__device__ __forceinline__ float newton_factor(float d, float x) {
    float f = fmaf(-d, x, 2.0f);
    return fminf(fmaxf(f, 0.5f), 1.5f);
}

// R11 configuration — the measured optimum of the occupancy/register trade-off
// (12w@168r=64us, 16w@128r=61.9us, 20w@96r=97us spill wall). 4 CTAs/SM,
// 128-reg cap, cold offsets in smem, hot loop fully register-resident.
__global__ __launch_bounds__(128, 4) void ol_main_kernel(
    const float* __restrict__ outp_g,
    const float* __restrict__ tgt_g,
    const float* __restrict__ msk_g,
    float* __restrict__ result,
    int npix)
{
    __shared__ float s_oy[SN][128];   // offsets pre-scaled by log2(e), [m][tid]
    __shared__ float s_ox[SN][128];
    __shared__ float s_part[5][4];    // per-warp partials for the block reduction

    const int tid = threadIdx.x;
    int p = blockIdx.x * blockDim.x + tid;

    float negf = 0.f, posf = 0.f, sumsq = 0.f, pnsq = 0.f, lp = 0.f;

    if (p < npix) {
        const int b  = p >> 14;            // HWPIX = 16384
        const int hw = p & (HWPIX - 1);
        const int h  = hw >> 7;
        const int w  = hw & 127;

        const float* outp = outp_g + (size_t)b * 36 * HWPIX + hw;
        const float* tgtp = tgt_g  + (size_t)b * 20 * HWPIX + hw;
        const float* mskp = msk_g  + (size_t)b * 10 * HWPIX + hw;

        // ---- pos/neg from mask ----
        float msum = 0.f;
        #pragma unroll
        for (int s = 0; s < SN; s++) msum += mskp[s * HWPIX];
        posf = (msum >= 1.0f) ? 1.0f : 0.0f;
        negf = 1.0f - posf;

        // ---- offsets (scaled by log2(e)); register copies die at loop entry,
        //      smem copy serves the epilogue so they are not loop-carried ----
        float oys[SN], oxs[SN];
        #pragma unroll
        for (int m = 0; m < 18; m++) {
            const int head  = (m >= 9) ? 1 : 0;
            const int local = m - head * 9;
            const int i = local / 3;
            const int j = local - i * 3;
            const int cy = head * 18 + local;        // d=0
            const float vy = outp[cy * HWPIX];
            const float vx = outp[(cy + 9) * HWPIX]; // d=1
            sumsq += vy * vy + vx * vx;
            const float oyv = vy + (float)(i - 1) + (float)h;
            const float oxv = vx + (float)(j - 1) + (float)w;
            if (m < SN) {
                oys[m] = oyv * LOG2E; oxs[m] = oxv * LOG2E;
                s_oy[m][tid] = oys[m]; s_ox[m][tid] = oxs[m];
            } else {
                pnsq += oyv * oyv + oxv * oxv;
            }
        }

        // ---- Gibbs kernel K[s][m] = 2^(rmin - c2[s][m]) (row max = 1), packed over m ----
        unsigned long long K2[SN][5];
        #pragma unroll
        for (int s = 0; s < SN; s++) {
            const float tys = tgtp[s * HWPIX] * LOG2E;
            const float txs = tgtp[(SN + s) * HWPIX] * LOG2E;
            float c[SN];
            float rm = 3.4e38f;
            #pragma unroll
            for (int m = 0; m < SN; m++) {
                c[m] = fabsf(tys - oys[m]) + fabsf(txs - oxs[m]);
                rm = fminf(rm, c[m]);
            }
            #pragma unroll
            for (int k = 0; k < 5; k++)
                K2[s][k] = f2_pack(fex2(rm - c[2 * k]), fex2(rm - c[2 * k + 1]));
        }

        // ---- Sinkhorn, rescaled: fixed point alpha.(K beta) = 1, beta.(K^T alpha) = 1.
        //      WARMUP=4 exact-rcp iterations enter the Newton basin (2 was NOT enough:
        //      R13 diverged to NaN), then division-free Newton-coupled scaling. ----
        float alpha[SN];
        unsigned long long beta[5];
        #pragma unroll
        for (int k = 0; k < 5; k++) beta[k] = f2_pack(20.0f, 20.0f);  // v0 = 0

        #pragma unroll
        for (int wu = 0; wu < WARMUP; wu++) {
            #pragma unroll
            for (int s = 0; s < SN; s++) {
                unsigned long long t0 = f2_mul(K2[s][0], beta[0]);
                unsigned long long t1 = f2_mul(K2[s][1], beta[1]);
                t0 = f2_fma(K2[s][2], beta[2], t0);
                t1 = f2_fma(K2[s][3], beta[3], t1);
                t0 = f2_fma(K2[s][4], beta[4], t0);
                float lo, hi; f2_unpack(f2_add(t0, t1), lo, hi);
                alpha[s] = frcp(lo + hi);
            }
            unsigned long long e0[5], e1[5];
            {
                const unsigned long long a0 = f2_pack(alpha[0], alpha[0]);
                const unsigned long long a5 = f2_pack(alpha[5], alpha[5]);
                #pragma unroll
                for (int k = 0; k < 5; k++) {
                    e0[k] = f2_mul(K2[0][k], a0);
                    e1[k] = f2_mul(K2[5][k], a5);
                }
            }
            #pragma unroll
            for (int s = 1; s < 5; s++) {
                const unsigned long long aa = f2_pack(alpha[s], alpha[s]);
                const unsigned long long bb = f2_pack(alpha[s + 5], alpha[s + 5]);
                #pragma unroll
                for (int k = 0; k < 5; k++) {
                    e0[k] = f2_fma(K2[s][k], aa, e0[k]);
                    e1[k] = f2_fma(K2[s + 5][k], bb, e1[k]);
                }
            }
            #pragma unroll
            for (int k = 0; k < 5; k++) {
                float lo, hi; f2_unpack(f2_add(e0[k], e1[k]), lo, hi);
                beta[k] = f2_pack(frcp(lo), frcp(hi));
            }
        }

        // Newton-mode main loop; residual read off the Newton factor (|f-1| = |1 - d*alpha|).
        // Factors are clamped to [0.5, 1.5] -> recurrence is unconditionally stable.
        // eps = 5e-4: exit earliness bound keeps final loss error ~1e-4 (<< 1e-3 budget).
        int it = 0;
        while (true) {
            bool conv = true;
            #pragma unroll
            for (int s = 0; s < SN; s++) {
                unsigned long long t0 = f2_mul(K2[s][0], beta[0]);
                unsigned long long t1 = f2_mul(K2[s][1], beta[1]);
                t0 = f2_fma(K2[s][2], beta[2], t0);
                t1 = f2_fma(K2[s][3], beta[3], t1);
                t0 = f2_fma(K2[s][4], beta[4], t0);
                float lo, hi; f2_unpack(f2_add(t0, t1), lo, hi);
                const float d = lo + hi;
                const float f = newton_factor(d, alpha[s]);
                conv = conv && (fabsf(f - 1.0f) <= 5e-4f);
                alpha[s] *= f;
            }
            unsigned long long e0[5], e1[5];
            {
                const unsigned long long a0 = f2_pack(alpha[0], alpha[0]);
                const unsigned long long a5 = f2_pack(alpha[5], alpha[5]);
                #pragma unroll
                for (int k = 0; k < 5; k++) {
                    e0[k] = f2_mul(K2[0][k], a0);
                    e1[k] = f2_mul(K2[5][k], a5);
                }
            }
            #pragma unroll
            for (int s = 1; s < 5; s++) {
                const unsigned long long aa = f2_pack(alpha[s], alpha[s]);
                const unsigned long long bb = f2_pack(alpha[s + 5], alpha[s + 5]);
                #pragma unroll
                for (int k = 0; k < 5; k++) {
                    e0[k] = f2_fma(K2[s][k], aa, e0[k]);
                    e1[k] = f2_fma(K2[s + 5][k], bb, e1[k]);
                }
            }
            #pragma unroll
            for (int k = 0; k < 5; k++) {
                float lo, hi; f2_unpack(f2_add(e0[k], e1[k]), lo, hi);
                float b0, b1; f2_unpack(beta[k], b0, b1);
                b0 *= newton_factor(lo, b0);
                b1 *= newton_factor(hi, b1);
                beta[k] = f2_pack(b0, b1);
            }
            if (++it >= ITERS) break;
            if (__all_sync(__activemask(), conv)) break;
        }

        // ---- loss_pos = sum_s mask_s * alpha_s * sum_m K[s][m]*beta_m*cost[s][m]
        //      (offsets read back from smem; costs in log2 units, one LN2 rescale) ----
        #pragma unroll
        for (int s = 0; s < SN; s++) {
            const float tys = tgtp[s * HWPIX] * LOG2E;
            const float txs = tgtp[(SN + s) * HWPIX] * LOG2E;
            unsigned long long acc = 0ull;   // packed (0,0)
            #pragma unroll
            for (int k = 0; k < 5; k++) {
                const float c0 = fabsf(tys - s_oy[2 * k][tid])     + fabsf(txs - s_ox[2 * k][tid]);
                const float c1 = fabsf(tys - s_oy[2 * k + 1][tid]) + fabsf(txs - s_ox[2 * k + 1][tid]);
                acc = f2_fma(f2_mul(K2[s][k], beta[k]), f2_pack(c0, c1), acc);
            }
            float lo, hi; f2_unpack(acc, lo, hi);
            const float ms = mskp[s * HWPIX];  // reload (L2 hit)
            lp = fmaf(ms * alpha[s], lo + hi, lp);
        }
        lp *= LN2;
        sumsq *= negf;
        pnsq  *= posf;
    }

    // ---- hierarchical reduction: warp shuffle -> smem -> ONE thread's atomics
    //      onto 128B-padded accumulators (proven 8us win in R10) ----
    float vals[5] = { negf, posf, sumsq, pnsq, lp };
    const int wid = tid >> 5;
    const int lid = tid & 31;
    #pragma unroll
    for (int k = 0; k < 5; k++) {
        float v = vals[k];
        #pragma unroll
        for (int off = 16; off; off >>= 1)
            v += __shfl_xor_sync(0xffffffffu, v, off);
        if (lid == 0) s_part[k][wid] = v;
    }
    __syncthreads();
    if (tid < 5) {
        const float bsum = s_part[tid][0] + s_part[tid][1]
                         + s_part[tid][2] + s_part[tid][3];
        atomicAdd(&g_acc[tid * 16], (double)bsum);
    }

    // ---- fused finalize: last block computes the scalar result and resets state ----
    __syncthreads();
    if (tid == 0) {
        __threadfence();
        const unsigned t = atomicAdd(&g_ticket, 1u);
        if (t == gridDim.x - 1) {
            __threadfence();
            const double n_neg = g_acc[0 * 16];
            const double n_pos = g_acc[1 * 16];
            const double loss_neg     = sqrt(g_acc[2 * 16]) / n_neg;
            const double loss_pos_neg = sqrt(g_acc[3 * 16]) / n_pos;
            result[0] = (float)((loss_neg + loss_pos_neg) * 100.0
                                + g_acc[4 * 16] / (n_pos + 0.0001));
            #pragma unroll
            for (int k = 0; k < 5; k++) g_acc[k * 16] = 0.0;
            __threadfence();
            g_ticket = 0u;
        }
    }
}

extern "C" void kernel_launch(void* const* d_in, const int* in_sizes, int n_in,
                              void* d_out, int out_size) {
    const float* out_t  = (const float*)d_in[0];   // (B, 36, 128, 128)
    const float* target = (const float*)d_in[1];   // (B, 20, 128, 128)
    const float* mask   = (const float*)d_in[2];   // (B, 10, 128, 128)

    const int npix = in_sizes[2] / SN;             // B * H * W
    const int threads = 128;
    const int blocks = (npix + threads - 1) / threads;

    ol_main_kernel<<<blocks, threads>>>(out_t, target, mask, (float*)d_out, npix);
}

// round 16
// speedup vs baseline: 1.7962x; 1.1487x over previous
#include <cuda_runtime.h>
#include <math.h>

// Problem constants (fixed by reference setup_inputs)
#define SN      10
#define ITERS   100
#define WARMUP  4
#define HWPIX   (128*128)
#define LOG2E   1.4426950408889634f
#define LN2     0.6931471805599453f

// Global accumulators: [k*16] for k in 0..4 -> each on its own 128B line so the
// five atomic streams hit different LTS slices instead of serializing on one.
// [0]=n_neg [1]=n_pos [2]=sumsq_neg [3]=sumsq_posneg [4]=loss_pos
__device__ double g_acc[5 * 16] = {0};
__device__ unsigned int g_ticket = 0;

// ---- packed f32x2 helpers (Blackwell sm_100+) ----
__device__ __forceinline__ unsigned long long f2_mul(unsigned long long a, unsigned long long b) {
    unsigned long long d;
    asm("mul.rn.f32x2 %0, %1, %2;" : "=l"(d) : "l"(a), "l"(b));
    return d;
}
__device__ __forceinline__ unsigned long long f2_fma(unsigned long long a, unsigned long long b, unsigned long long c) {
    unsigned long long d;
    asm("fma.rn.f32x2 %0, %1, %2, %3;" : "=l"(d) : "l"(a), "l"(b), "l"(c));
    return d;
}
__device__ __forceinline__ unsigned long long f2_add(unsigned long long a, unsigned long long b) {
    unsigned long long d;
    asm("add.rn.f32x2 %0, %1, %2;" : "=l"(d) : "l"(a), "l"(b));
    return d;
}
__device__ __forceinline__ unsigned long long f2_pack(float lo, float hi) {
    unsigned long long d;
    asm("mov.b64 %0, {%1, %2};" : "=l"(d) : "f"(lo), "f"(hi));
    return d;
}
__device__ __forceinline__ void f2_unpack(unsigned long long v, float& lo, float& hi) {
    asm("mov.b64 {%0, %1}, %2;" : "=f"(lo), "=f"(hi) : "l"(v));
}
__device__ __forceinline__ float frcp(float x) {
    float y; asm("rcp.approx.f32 %0, %1;" : "=f"(y) : "f"(x)); return y;
}
__device__ __forceinline__ float fex2(float x) {
    float y; asm("ex2.approx.f32 %0, %1;" : "=f"(y) : "f"(x)); return y;
}

// R11 configuration — measured optimum of the occupancy/register trade-off
// (12w@168r=64us, 16w@128r=61.9us, 20w@96r=97us spill wall). 4 CTAs/SM,
// 128-reg cap, cold state in smem, hot loop fully register-resident.
// New this round: targets and mask cached in smem so the epilogue issues
// zero strided global loads (they were ~30 L2/DRAM-latency stalls on the tail).
__global__ __launch_bounds__(128, 4) void ol_main_kernel(
    const float* __restrict__ outp_g,
    const float* __restrict__ tgt_g,
    const float* __restrict__ msk_g,
    float* __restrict__ result,
    int npix)
{
    __shared__ float s_oy[SN][128];   // offsets, pre-scaled by log2(e), [m][tid]
    __shared__ float s_ox[SN][128];
    __shared__ float s_ty[SN][128];   // targets, pre-scaled by log2(e), [s][tid]
    __shared__ float s_tx[SN][128];
    __shared__ float s_ms[SN][128];   // mask values, [s][tid]
    __shared__ float s_part[5][4];    // per-warp partials for the block reduction

    const int tid = threadIdx.x;
    int p = blockIdx.x * blockDim.x + tid;

    float negf = 0.f, posf = 0.f, sumsq = 0.f, pnsq = 0.f, lp = 0.f;

    if (p < npix) {
        const int b  = p >> 14;            // HWPIX = 16384
        const int hw = p & (HWPIX - 1);
        const int h  = hw >> 7;
        const int w  = hw & 127;

        const float* outp = outp_g + (size_t)b * 36 * HWPIX + hw;
        const float* tgtp = tgt_g  + (size_t)b * 20 * HWPIX + hw;
        const float* mskp = msk_g  + (size_t)b * 10 * HWPIX + hw;

        // ---- pos/neg from mask (values cached in smem for the epilogue) ----
        float msum = 0.f;
        #pragma unroll
        for (int s = 0; s < SN; s++) {
            const float ms = mskp[s * HWPIX];
            s_ms[s][tid] = ms;
            msum += ms;
        }
        posf = (msum >= 1.0f) ? 1.0f : 0.0f;
        negf = 1.0f - posf;

        // ---- offsets (scaled by log2(e)); register copies die at loop entry,
        //      smem copy serves the epilogue so they are not loop-carried ----
        float oys[SN], oxs[SN];
        #pragma unroll
        for (int m = 0; m < 18; m++) {
            const int head  = (m >= 9) ? 1 : 0;
            const int local = m - head * 9;
            const int i = local / 3;
            const int j = local - i * 3;
            const int cy = head * 18 + local;        // d=0
            const float vy = outp[cy * HWPIX];
            const float vx = outp[(cy + 9) * HWPIX]; // d=1
            sumsq += vy * vy + vx * vx;
            const float oyv = vy + (float)(i - 1) + (float)h;
            const float oxv = vx + (float)(j - 1) + (float)w;
            if (m < SN) {
                oys[m] = oyv * LOG2E; oxs[m] = oxv * LOG2E;
                s_oy[m][tid] = oys[m]; s_ox[m][tid] = oxs[m];
            } else {
                pnsq += oyv * oyv + oxv * oxv;
            }
        }

        // ---- Gibbs kernel K[s][m] = 2^(rmin - c2[s][m]) (row max = 1), packed over m.
        //      Scaled targets cached in smem for the epilogue. ----
        unsigned long long K2[SN][5];
        #pragma unroll
        for (int s = 0; s < SN; s++) {
            const float tys = tgtp[s * HWPIX] * LOG2E;
            const float txs = tgtp[(SN + s) * HWPIX] * LOG2E;
            s_ty[s][tid] = tys;
            s_tx[s][tid] = txs;
            float c[SN];
            float rm = 3.4e38f;
            #pragma unroll
            for (int m = 0; m < SN; m++) {
                c[m] = fabsf(tys - oys[m]) + fabsf(txs - oxs[m]);
                rm = fminf(rm, c[m]);
            }
            #pragma unroll
            for (int k = 0; k < 5; k++)
                K2[s][k] = f2_pack(fex2(rm - c[2 * k]), fex2(rm - c[2 * k + 1]));
        }

        // ---- Sinkhorn, rescaled: fixed point alpha.(K beta) = 1, beta.(K^T alpha) = 1.
        //      WARMUP=4 exact-rcp iterations enter the Newton basin (2 was NOT
        //      enough: R13 NaN), then division-free Newton-coupled scaling. ----
        float alpha[SN];
        unsigned long long beta[5];
        #pragma unroll
        for (int k = 0; k < 5; k++) beta[k] = f2_pack(20.0f, 20.0f);  // v0 = 0

        #pragma unroll
        for (int wu = 0; wu < WARMUP; wu++) {
            #pragma unroll
            for (int s = 0; s < SN; s++) {
                unsigned long long t0 = f2_mul(K2[s][0], beta[0]);
                unsigned long long t1 = f2_mul(K2[s][1], beta[1]);
                t0 = f2_fma(K2[s][2], beta[2], t0);
                t1 = f2_fma(K2[s][3], beta[3], t1);
                t0 = f2_fma(K2[s][4], beta[4], t0);
                float lo, hi; f2_unpack(f2_add(t0, t1), lo, hi);
                alpha[s] = frcp(lo + hi);
            }
            unsigned long long e0[5], e1[5];
            {
                const unsigned long long a0 = f2_pack(alpha[0], alpha[0]);
                const unsigned long long a5 = f2_pack(alpha[5], alpha[5]);
                #pragma unroll
                for (int k = 0; k < 5; k++) {
                    e0[k] = f2_mul(K2[0][k], a0);
                    e1[k] = f2_mul(K2[5][k], a5);
                }
            }
            #pragma unroll
            for (int s = 1; s < 5; s++) {
                const unsigned long long aa = f2_pack(alpha[s], alpha[s]);
                const unsigned long long bb = f2_pack(alpha[s + 5], alpha[s + 5]);
                #pragma unroll
                for (int k = 0; k < 5; k++) {
                    e0[k] = f2_fma(K2[s][k], aa, e0[k]);
                    e1[k] = f2_fma(K2[s + 5][k], bb, e1[k]);
                }
            }
            #pragma unroll
            for (int k = 0; k < 5; k++) {
                float lo, hi; f2_unpack(f2_add(e0[k], e1[k]), lo, hi);
                beta[k] = f2_pack(frcp(lo), frcp(hi));
            }
        }

        // Newton-mode main loop; residual read off the Newton factor (|f-1| = |1 - d*alpha|).
        int it = 0;
        while (true) {
            bool conv = true;
            #pragma unroll
            for (int s = 0; s < SN; s++) {
                unsigned long long t0 = f2_mul(K2[s][0], beta[0]);
                unsigned long long t1 = f2_mul(K2[s][1], beta[1]);
                t0 = f2_fma(K2[s][2], beta[2], t0);
                t1 = f2_fma(K2[s][3], beta[3], t1);
                t0 = f2_fma(K2[s][4], beta[4], t0);
                float lo, hi; f2_unpack(f2_add(t0, t1), lo, hi);
                const float d = lo + hi;
                const float f = fmaf(-d, alpha[s], 2.0f);   // Newton factor
                conv = conv && (fabsf(f - 1.0f) <= 5e-4f);
                alpha[s] *= f;
            }
            unsigned long long e0[5], e1[5];
            {
                const unsigned long long a0 = f2_pack(alpha[0], alpha[0]);
                const unsigned long long a5 = f2_pack(alpha[5], alpha[5]);
                #pragma unroll
                for (int k = 0; k < 5; k++) {
                    e0[k] = f2_mul(K2[0][k], a0);
                    e1[k] = f2_mul(K2[5][k], a5);
                }
            }
            #pragma unroll
            for (int s = 1; s < 5; s++) {
                const unsigned long long aa = f2_pack(alpha[s], alpha[s]);
                const unsigned long long bb = f2_pack(alpha[s + 5], alpha[s + 5]);
                #pragma unroll
                for (int k = 0; k < 5; k++) {
                    e0[k] = f2_fma(K2[s][k], aa, e0[k]);
                    e1[k] = f2_fma(K2[s + 5][k], bb, e1[k]);
                }
            }
            #pragma unroll
            for (int k = 0; k < 5; k++) {
                float lo, hi; f2_unpack(f2_add(e0[k], e1[k]), lo, hi);
                float b0, b1; f2_unpack(beta[k], b0, b1);
                b0 = b0 * fmaf(-lo, b0, 2.0f);   // Newton rcp step for beta
                b1 = b1 * fmaf(-hi, b1, 2.0f);
                beta[k] = f2_pack(b0, b1);
            }
            if (++it >= ITERS) break;
            if (__all_sync(__activemask(), conv)) break;
        }

        // ---- loss_pos = sum_s mask_s * alpha_s * sum_m K[s][m]*beta_m*cost[s][m]
        //      Entirely smem-fed: no global loads on the kernel tail. ----
        #pragma unroll
        for (int s = 0; s < SN; s++) {
            const float tys = s_ty[s][tid];
            const float txs = s_tx[s][tid];
            unsigned long long acc = 0ull;   // packed (0,0)
            #pragma unroll
            for (int k = 0; k < 5; k++) {
                const float c0 = fabsf(tys - s_oy[2 * k][tid])     + fabsf(txs - s_ox[2 * k][tid]);
                const float c1 = fabsf(tys - s_oy[2 * k + 1][tid]) + fabsf(txs - s_ox[2 * k + 1][tid]);
                acc = f2_fma(f2_mul(K2[s][k], beta[k]), f2_pack(c0, c1), acc);
            }
            float lo, hi; f2_unpack(acc, lo, hi);
            lp = fmaf(s_ms[s][tid] * alpha[s], lo + hi, lp);
        }
        lp *= LN2;
        sumsq *= negf;
        pnsq  *= posf;
    }

    // ---- hierarchical reduction: warp shuffle -> smem -> ONE thread's atomics
    //      onto 128B-padded accumulators (proven 8us win in R10) ----
    float vals[5] = { negf, posf, sumsq, pnsq, lp };
    const int wid = tid >> 5;
    const int lid = tid & 31;
    #pragma unroll
    for (int k = 0; k < 5; k++) {
        float v = vals[k];
        #pragma unroll
        for (int off = 16; off; off >>= 1)
            v += __shfl_xor_sync(0xffffffffu, v, off);
        if (lid == 0) s_part[k][wid] = v;
    }
    __syncthreads();
    if (tid < 5) {
        const float bsum = s_part[tid][0] + s_part[tid][1]
                         + s_part[tid][2] + s_part[tid][3];
        atomicAdd(&g_acc[tid * 16], (double)bsum);
    }

    // ---- fused finalize: last block computes the scalar result and resets state ----
    __syncthreads();
    if (tid == 0) {
        __threadfence();
        const unsigned t = atomicAdd(&g_ticket, 1u);
        if (t == gridDim.x - 1) {
            __threadfence();
            const double n_neg = g_acc[0 * 16];
            const double n_pos = g_acc[1 * 16];
            const double loss_neg     = sqrt(g_acc[2 * 16]) / n_neg;
            const double loss_pos_neg = sqrt(g_acc[3 * 16]) / n_pos;
            result[0] = (float)((loss_neg + loss_pos_neg) * 100.0
                                + g_acc[4 * 16] / (n_pos + 0.0001));
            #pragma unroll
            for (int k = 0; k < 5; k++) g_acc[k * 16] = 0.0;
            __threadfence();
            g_ticket = 0u;
        }
    }
}

extern "C" void kernel_launch(void* const* d_in, const int* in_sizes, int n_in,
                              void* d_out, int out_size) {
    const float* out_t  = (const float*)d_in[0];   // (B, 36, 128, 128)
    const float* target = (const float*)d_in[1];   // (B, 20, 128, 128)
    const float* mask   = (const float*)d_in[2];   // (B, 10, 128, 128)

    const int npix = in_sizes[2] / SN;             // B * H * W
    const int threads = 128;
    const int blocks = (npix + threads - 1) / threads;

    ol_main_kernel<<<blocks, threads>>>(out_t, target, mask, (float*)d_out, npix);
}

// round 17
// speedup vs baseline: 1.8751x; 1.0439x over previous
#include <cuda_runtime.h>
#include <math.h>

// Problem constants (fixed by reference setup_inputs)
#define SN      10
#define ITERS   100
#define WARMUP  4
#define HWPIX   (128*128)
#define LOG2E   1.4426950408889634f
#define LN2     0.6931471805599453f
#define OMEGA   1.3f   // overrelaxation for the alpha update (clamped -> NaN-safe)

// Global accumulators: [k*16] for k in 0..4 -> each on its own 128B line so the
// five atomic streams hit different LTS slices instead of serializing on one.
// [0]=n_neg [1]=n_pos [2]=sumsq_neg [3]=sumsq_posneg [4]=loss_pos
__device__ double g_acc[5 * 16] = {0};
__device__ unsigned int g_ticket = 0;

// ---- packed f32x2 helpers (Blackwell sm_100+) ----
__device__ __forceinline__ unsigned long long f2_mul(unsigned long long a, unsigned long long b) {
    unsigned long long d;
    asm("mul.rn.f32x2 %0, %1, %2;" : "=l"(d) : "l"(a), "l"(b));
    return d;
}
__device__ __forceinline__ unsigned long long f2_fma(unsigned long long a, unsigned long long b, unsigned long long c) {
    unsigned long long d;
    asm("fma.rn.f32x2 %0, %1, %2, %3;" : "=l"(d) : "l"(a), "l"(b), "l"(c));
    return d;
}
__device__ __forceinline__ unsigned long long f2_add(unsigned long long a, unsigned long long b) {
    unsigned long long d;
    asm("add.rn.f32x2 %0, %1, %2;" : "=l"(d) : "l"(a), "l"(b));
    return d;
}
__device__ __forceinline__ unsigned long long f2_pack(float lo, float hi) {
    unsigned long long d;
    asm("mov.b64 %0, {%1, %2};" : "=l"(d) : "f"(lo), "f"(hi));
    return d;
}
__device__ __forceinline__ void f2_unpack(unsigned long long v, float& lo, float& hi) {
    asm("mov.b64 {%0, %1}, %2;" : "=f"(lo), "=f"(hi) : "l"(v));
}
__device__ __forceinline__ float frcp(float x) {
    float y; asm("rcp.approx.f32 %0, %1;" : "=f"(y) : "f"(x)); return y;
}
__device__ __forceinline__ float fex2(float x) {
    float y; asm("ex2.approx.f32 %0, %1;" : "=f"(y) : "f"(x)); return y;
}

// Packed constant (2.0f, 2.0f) for the beta Newton step.
#define TWO2 0x4000000040000000ULL

// R15 configuration (proven): 4 CTAs/SM, 128-reg cap, all epilogue inputs
// cached in smem, hot loop register-resident.
// New this round: (a) overrelaxed alpha update (fewer iterations, same fixed
// point), (b) negated-alpha representation -> fully packed beta Newton step.
__global__ __launch_bounds__(128, 4) void ol_main_kernel(
    const float* __restrict__ outp_g,
    const float* __restrict__ tgt_g,
    const float* __restrict__ msk_g,
    float* __restrict__ result,
    int npix)
{
    __shared__ float s_oy[SN][128];   // offsets, pre-scaled by log2(e), [m][tid]
    __shared__ float s_ox[SN][128];
    __shared__ float s_ty[SN][128];   // targets, pre-scaled by log2(e), [s][tid]
    __shared__ float s_tx[SN][128];
    __shared__ float s_ms[SN][128];   // mask values, [s][tid]
    __shared__ float s_part[5][4];    // per-warp partials for the block reduction

    const int tid = threadIdx.x;
    int p = blockIdx.x * blockDim.x + tid;

    float negf = 0.f, posf = 0.f, sumsq = 0.f, pnsq = 0.f, lp = 0.f;

    if (p < npix) {
        const int b  = p >> 14;            // HWPIX = 16384
        const int hw = p & (HWPIX - 1);
        const int h  = hw >> 7;
        const int w  = hw & 127;

        const float* outp = outp_g + (size_t)b * 36 * HWPIX + hw;
        const float* tgtp = tgt_g  + (size_t)b * 20 * HWPIX + hw;
        const float* mskp = msk_g  + (size_t)b * 10 * HWPIX + hw;

        // ---- pos/neg from mask (values cached in smem for the epilogue) ----
        float msum = 0.f;
        #pragma unroll
        for (int s = 0; s < SN; s++) {
            const float ms = mskp[s * HWPIX];
            s_ms[s][tid] = ms;
            msum += ms;
        }
        posf = (msum >= 1.0f) ? 1.0f : 0.0f;
        negf = 1.0f - posf;

        // ---- offsets (scaled by log2(e)); register copies die at loop entry,
        //      smem copy serves the epilogue so they are not loop-carried ----
        float oys[SN], oxs[SN];
        #pragma unroll
        for (int m = 0; m < 18; m++) {
            const int head  = (m >= 9) ? 1 : 0;
            const int local = m - head * 9;
            const int i = local / 3;
            const int j = local - i * 3;
            const int cy = head * 18 + local;        // d=0
            const float vy = outp[cy * HWPIX];
            const float vx = outp[(cy + 9) * HWPIX]; // d=1
            sumsq += vy * vy + vx * vx;
            const float oyv = vy + (float)(i - 1) + (float)h;
            const float oxv = vx + (float)(j - 1) + (float)w;
            if (m < SN) {
                oys[m] = oyv * LOG2E; oxs[m] = oxv * LOG2E;
                s_oy[m][tid] = oys[m]; s_ox[m][tid] = oxs[m];
            } else {
                pnsq += oyv * oyv + oxv * oxv;
            }
        }

        // ---- Gibbs kernel K[s][m] = 2^(rmin - c2[s][m]) (row max = 1), packed over m.
        //      Scaled targets cached in smem for the epilogue. ----
        unsigned long long K2[SN][5];
        #pragma unroll
        for (int s = 0; s < SN; s++) {
            const float tys = tgtp[s * HWPIX] * LOG2E;
            const float txs = tgtp[(SN + s) * HWPIX] * LOG2E;
            s_ty[s][tid] = tys;
            s_tx[s][tid] = txs;
            float c[SN];
            float rm = 3.4e38f;
            #pragma unroll
            for (int m = 0; m < SN; m++) {
                c[m] = fabsf(tys - oys[m]) + fabsf(txs - oxs[m]);
                rm = fminf(rm, c[m]);
            }
            #pragma unroll
            for (int k = 0; k < 5; k++)
                K2[s][k] = f2_pack(fex2(rm - c[2 * k]), fex2(rm - c[2 * k + 1]));
        }

        // ---- Sinkhorn, rescaled: fixed point alpha.(K beta) = 1, beta.(K^T alpha) = 1.
        //      Representation: alphan = -alpha (so the col-pass accumulator
        //      e = K^T alphan is pre-negated and the beta Newton step is fully
        //      packed: g = fma(e, beta, 2), beta *= g).
        //      WARMUP=4 exact-rcp iterations enter the Newton basin (2 was NOT
        //      enough: R13 NaN), then division-free Newton-coupled scaling. ----
        float alphan[SN];
        unsigned long long beta[5];
        #pragma unroll
        for (int k = 0; k < 5; k++) beta[k] = f2_pack(20.0f, 20.0f);  // v0 = 0

        #pragma unroll
        for (int wu = 0; wu < WARMUP; wu++) {
            #pragma unroll
            for (int s = 0; s < SN; s++) {
                unsigned long long t0 = f2_mul(K2[s][0], beta[0]);
                unsigned long long t1 = f2_mul(K2[s][1], beta[1]);
                t0 = f2_fma(K2[s][2], beta[2], t0);
                t1 = f2_fma(K2[s][3], beta[3], t1);
                t0 = f2_fma(K2[s][4], beta[4], t0);
                float lo, hi; f2_unpack(f2_add(t0, t1), lo, hi);
                alphan[s] = frcp(-lo - hi);          // alphan = -1/d
            }
            unsigned long long e0[5], e1[5];
            {
                const unsigned long long a0 = f2_pack(alphan[0], alphan[0]);
                const unsigned long long a5 = f2_pack(alphan[5], alphan[5]);
                #pragma unroll
                for (int k = 0; k < 5; k++) {
                    e0[k] = f2_mul(K2[0][k], a0);
                    e1[k] = f2_mul(K2[5][k], a5);
                }
            }
            #pragma unroll
            for (int s = 1; s < 5; s++) {
                const unsigned long long aa = f2_pack(alphan[s], alphan[s]);
                const unsigned long long bb = f2_pack(alphan[s + 5], alphan[s + 5]);
                #pragma unroll
                for (int k = 0; k < 5; k++) {
                    e0[k] = f2_fma(K2[s][k], aa, e0[k]);
                    e1[k] = f2_fma(K2[s + 5][k], bb, e1[k]);
                }
            }
            #pragma unroll
            for (int k = 0; k < 5; k++) {
                float lo, hi; f2_unpack(f2_add(e0[k], e1[k]), lo, hi);
                beta[k] = f2_pack(frcp(-lo), frcp(-hi));   // e is negated
            }
        }

        // Newton-mode main loop with overrelaxation on alpha.
        // Raw residual f = 2 - d*alpha = fma(d, alphan, 2); exit on |f-1| <= eps.
        // Relaxed factor f' = 1 + OMEGA*(f-1), clamped to [0.5, 1.5]: same fixed
        // point, faster contraction, and the clamp keeps e.b < 2 so the packed
        // beta Newton step below can never leave its basin (no NaN path).
        int it = 0;
        while (true) {
            bool conv = true;
            #pragma unroll
            for (int s = 0; s < SN; s++) {
                unsigned long long t0 = f2_mul(K2[s][0], beta[0]);
                unsigned long long t1 = f2_mul(K2[s][1], beta[1]);
                t0 = f2_fma(K2[s][2], beta[2], t0);
                t1 = f2_fma(K2[s][3], beta[3], t1);
                t0 = f2_fma(K2[s][4], beta[4], t0);
                float lo, hi; f2_unpack(f2_add(t0, t1), lo, hi);
                const float d = lo + hi;
                const float f = fmaf(d, alphan[s], 2.0f);       // raw Newton factor
                conv = conv && (fabsf(f - 1.0f) <= 5e-4f);
                float fr = fmaf(OMEGA, f, 1.0f - OMEGA);        // overrelaxed
                fr = fminf(fmaxf(fr, 0.5f), 1.5f);              // basin-safe
                alphan[s] *= fr;
            }
            unsigned long long e0[5], e1[5];
            {
                const unsigned long long a0 = f2_pack(alphan[0], alphan[0]);
                const unsigned long long a5 = f2_pack(alphan[5], alphan[5]);
                #pragma unroll
                for (int k = 0; k < 5; k++) {
                    e0[k] = f2_mul(K2[0][k], a0);
                    e1[k] = f2_mul(K2[5][k], a5);
                }
            }
            #pragma unroll
            for (int s = 1; s < 5; s++) {
                const unsigned long long aa = f2_pack(alphan[s], alphan[s]);
                const unsigned long long bb = f2_pack(alphan[s + 5], alphan[s + 5]);
                #pragma unroll
                for (int k = 0; k < 5; k++) {
                    e0[k] = f2_fma(K2[s][k], aa, e0[k]);
                    e1[k] = f2_fma(K2[s + 5][k], bb, e1[k]);
                }
            }
            // Fully packed beta Newton: e = K^T alphan is NEGATED, so
            // g = fma(e, beta, 2) = 2 - (K^T alpha).beta, beta *= g.
            #pragma unroll
            for (int k = 0; k < 5; k++) {
                const unsigned long long e = f2_add(e0[k], e1[k]);
                const unsigned long long g = f2_fma(e, beta[k], TWO2);
                beta[k] = f2_mul(beta[k], g);
            }
            if (++it >= ITERS) break;
            if (__all_sync(__activemask(), conv)) break;
        }

        // ---- loss_pos = sum_s mask_s * alpha_s * sum_m K[s][m]*beta_m*cost[s][m]
        //      Entirely smem-fed; alpha = -alphan folded into the final fma. ----
        #pragma unroll
        for (int s = 0; s < SN; s++) {
            const float tys = s_ty[s][tid];
            const float txs = s_tx[s][tid];
            unsigned long long acc = 0ull;   // packed (0,0)
            #pragma unroll
            for (int k = 0; k < 5; k++) {
                const float c0 = fabsf(tys - s_oy[2 * k][tid])     + fabsf(txs - s_ox[2 * k][tid]);
                const float c1 = fabsf(tys - s_oy[2 * k + 1][tid]) + fabsf(txs - s_ox[2 * k + 1][tid]);
                acc = f2_fma(f2_mul(K2[s][k], beta[k]), f2_pack(c0, c1), acc);
            }
            float lo, hi; f2_unpack(acc, lo, hi);
            lp = fmaf(s_ms[s][tid] * alphan[s], -lo - hi, lp);   // (-an)*(lo+hi)
        }
        lp *= LN2;
        sumsq *= negf;
        pnsq  *= posf;
    }

    // ---- hierarchical reduction: warp shuffle -> smem -> ONE thread's atomics
    //      onto 128B-padded accumulators (proven 8us win in R10) ----
    float vals[5] = { negf, posf, sumsq, pnsq, lp };
    const int wid = tid >> 5;
    const int lid = tid & 31;
    #pragma unroll
    for (int k = 0; k < 5; k++) {
        float v = vals[k];
        #pragma unroll
        for (int off = 16; off; off >>= 1)
            v += __shfl_xor_sync(0xffffffffu, v, off);
        if (lid == 0) s_part[k][wid] = v;
    }
    __syncthreads();
    if (tid < 5) {
        const float bsum = s_part[tid][0] + s_part[tid][1]
                         + s_part[tid][2] + s_part[tid][3];
        atomicAdd(&g_acc[tid * 16], (double)bsum);
    }

    // ---- fused finalize: last block computes the scalar result and resets state ----
    __syncthreads();
    if (tid == 0) {
        __threadfence();
        const unsigned t = atomicAdd(&g_ticket, 1u);
        if (t == gridDim.x - 1) {
            __threadfence();
            const double n_neg = g_acc[0 * 16];
            const double n_pos = g_acc[1 * 16];
            const double loss_neg     = sqrt(g_acc[2 * 16]) / n_neg;
            const double loss_pos_neg = sqrt(g_acc[3 * 16]) / n_pos;
            result[0] = (float)((loss_neg + loss_pos_neg) * 100.0
                                + g_acc[4 * 16] / (n_pos + 0.0001));
            #pragma unroll
            for (int k = 0; k < 5; k++) g_acc[k * 16] = 0.0;
            __threadfence();
            g_ticket = 0u;
        }
    }
}

extern "C" void kernel_launch(void* const* d_in, const int* in_sizes, int n_in,
                              void* d_out, int out_size) {
    const float* out_t  = (const float*)d_in[0];   // (B, 36, 128, 128)
    const float* target = (const float*)d_in[1];   // (B, 20, 128, 128)
    const float* mask   = (const float*)d_in[2];   // (B, 10, 128, 128)

    const int npix = in_sizes[2] / SN;             // B * H * W
    const int threads = 128;
    const int blocks = (npix + threads - 1) / threads;

    ol_main_kernel<<<blocks, threads>>>(out_t, target, mask, (float*)d_out, npix);
}